// round 13
// baseline (speedup 1.0000x reference)
#include <cuda_runtime.h>
#include <cstdint>

#define NL 7
#define BATCH 524288
#define TPB 128
#define PPB (TPB * 2)           // poses per block = 256
#define GRIDN (BATCH / PPB)     // 2048
#define LPOSF (PPB * 3)         // floats per link in pos staging = 768
#define QBYTES (PPB * NL * 4)   // q bytes per block = 7168
#define QCHUNKS (QBYTES / 32)   // 224

typedef unsigned long long ull;

__device__ __forceinline__ ull f2pk(float lo, float hi) {
    ull r; asm("mov.b64 %0, {%1, %2};" : "=l"(r) : "f"(lo), "f"(hi)); return r;
}
__device__ __forceinline__ void f2upk(ull v, float& lo, float& hi) {
    asm("mov.b64 {%0, %1}, %2;" : "=f"(lo), "=f"(hi) : "l"(v));
}
__device__ __forceinline__ ull f2fma(ull a, ull b, ull c) {
    ull d; asm("fma.rn.f32x2 %0, %1, %2, %3;" : "=l"(d) : "l"(a), "l"(b), "l"(c)); return d;
}
__device__ __forceinline__ ull f2mul(ull a, ull b) {
    ull d; asm("mul.rn.f32x2 %0, %1, %2;" : "=l"(d) : "l"(a), "l"(b)); return d;
}
__device__ __forceinline__ ull f2add(ull a, ull b) {
    ull d; asm("add.rn.f32x2 %0, %1, %2;" : "=l"(d) : "l"(a), "l"(b)); return d;
}
__device__ __forceinline__ void ldg32_evict_last(const void* p, uint32_t r[8]) {
    asm volatile("ld.global.nc.L2::evict_last.v8.b32 {%0,%1,%2,%3,%4,%5,%6,%7}, [%8];"
                 : "=r"(r[0]), "=r"(r[1]), "=r"(r[2]), "=r"(r[3]),
                   "=r"(r[4]), "=r"(r[5]), "=r"(r[6]), "=r"(r[7])
                 : "l"(p));
}

struct PState { ull PX, PY, PZ, PW, TX, TY, TZ; };

// One packed (2-pose) chain step. Bit-identical per lane to the frozen scalar
// tree (rel_err 2.3156e-4) — operand order must not change.
template<int L>
__device__ __forceinline__ void fk_step_pk(PState& st, ull FX, ull FY, ull FZ, ull FW,
                                           ull VX, ull VY, ull VZ, ull S, ull C, ull NS,
                                           ull M1, ull TWO)
{
    ull PX = st.PX, PY = st.PY, PZ = st.PZ, PW = st.PW;
    ull NPX = f2mul(PX, M1);
    ull NPY = f2mul(PY, M1);
    ull NPZ = f2mul(PZ, M1);

    // t += rotate(p, tf)
    ull C1X = f2fma(PY, VZ, f2mul(NPZ, VY));
    ull C1Y = f2fma(PZ, VX, f2mul(NPX, VZ));
    ull C1Z = f2fma(PX, VY, f2mul(NPY, VX));
    ull C2X = f2fma(PW, C1X, f2fma(PY, C1Z, f2mul(NPZ, C1Y)));
    ull C2Y = f2fma(PW, C1Y, f2fma(PZ, C1X, f2mul(NPX, C1Z)));
    ull C2Z = f2fma(PW, C1Z, f2fma(PX, C1Y, f2mul(NPY, C1X)));
    st.TX = f2fma(TWO, C2X, f2add(st.TX, VX));
    st.TY = f2fma(TWO, C2Y, f2add(st.TY, VY));
    st.TZ = f2fma(TWO, C2Z, f2add(st.TZ, VZ));

    // m = p (x) qf
    ull MW = f2fma(PW, FW, f2fma(NPX, FX, f2fma(NPY, FY, f2mul(NPZ, FZ))));
    ull MX = f2fma(PW, FX, f2fma(PX,  FW, f2fma(PY,  FZ, f2mul(NPZ, FY))));
    ull MY = f2fma(PW, FY, f2fma(NPX, FZ, f2fma(PY,  FW, f2mul(PZ,  FX))));
    ull MZ = f2fma(PW, FZ, f2fma(PX,  FY, f2fma(NPY, FX, f2mul(PZ,  FW))));

    if ((L & 1) == 0) {   // axis z
        st.PW = f2fma(MW, C, f2mul(MZ, NS));
        st.PX = f2fma(MX, C, f2mul(MY, S));
        st.PY = f2fma(MY, C, f2mul(MX, NS));
        st.PZ = f2fma(MW, S, f2mul(MZ, C));
    } else {              // axis y
        st.PW = f2fma(MW, C, f2mul(MY, NS));
        st.PX = f2fma(MX, C, f2mul(MZ, NS));
        st.PY = f2fma(MW, S, f2mul(MY, C));
        st.PZ = f2fma(MZ, C, f2mul(MX, S));
    }
}

__global__ __launch_bounds__(TPB, 8)
void fk_pk3_kernel(const float* __restrict__ q,
                   const float* __restrict__ rot_fixed,
                   const float* __restrict__ trans_fixed,
                   float* __restrict__ out)
{
    __shared__ ull sF[NL * 4];
    __shared__ ull sV[NL * 3];
    __shared__ __align__(16) float sQ[PPB * NL];        // 7 KB (live all kernel)
    __shared__ __align__(16) float sPos[4 * LPOSF];     // 12 KB (4 link slots)

    const int tid  = threadIdx.x;
    const int base = blockIdx.x * PPB;

    // ---- coalesced q load, pinned in L2 (evict_last, 32B chunks) ----
    {
        const char* gq = (const char*)(q + (size_t)base * NL);
        uint32_t r[8];
        ldg32_evict_last(gq + tid * 32, r);
        float4* sq4 = (float4*)((char*)sQ + tid * 32);
        sq4[0] = make_float4(__uint_as_float(r[0]), __uint_as_float(r[1]),
                             __uint_as_float(r[2]), __uint_as_float(r[3]));
        sq4[1] = make_float4(__uint_as_float(r[4]), __uint_as_float(r[5]),
                             __uint_as_float(r[6]), __uint_as_float(r[7]));
        if (tid < QCHUNKS - TPB) {   // remaining 96 chunks
            ldg32_evict_last(gq + (tid + TPB) * 32, r);
            float4* sq4b = (float4*)((char*)sQ + (tid + TPB) * 32);
            sq4b[0] = make_float4(__uint_as_float(r[0]), __uint_as_float(r[1]),
                                  __uint_as_float(r[2]), __uint_as_float(r[3]));
            sq4b[1] = make_float4(__uint_as_float(r[4]), __uint_as_float(r[5]),
                                  __uint_as_float(r[6]), __uint_as_float(r[7]));
        }
    }

    // ---- fixed params -> packed broadcast (frozen values) ----
    if (tid < NL) {
        const float* R = rot_fixed + tid * 9;
        float r00 = R[0], r01 = R[1], r02 = R[2];
        float r10 = R[3], r11 = R[4], r12 = R[5];
        float r20 = R[6], r21 = R[7], r22 = R[8];
        const float eps = 1e-9f;
        float qw = 0.5f * sqrtf(fmaxf(1.f + r00 + r11 + r22, eps));
        float qx = 0.5f * sqrtf(fmaxf(1.f + r00 - r11 - r22, eps));
        float qy = 0.5f * sqrtf(fmaxf(1.f - r00 + r11 - r22, eps));
        float qz = 0.5f * sqrtf(fmaxf(1.f - r00 - r11 + r22, eps));
        qx = copysignf(qx, r21 - r12);
        qy = copysignf(qy, r02 - r20);
        qz = copysignf(qz, r10 - r01);
        sF[tid * 4 + 0] = f2pk(qx, qx);
        sF[tid * 4 + 1] = f2pk(qy, qy);
        sF[tid * 4 + 2] = f2pk(qz, qz);
        sF[tid * 4 + 3] = f2pk(qw, qw);
        const float* tf = trans_fixed + tid * 3;
        sV[tid * 3 + 0] = f2pk(tf[0], tf[0]);
        sV[tid * 3 + 1] = f2pk(tf[1], tf[1]);
        sV[tid * 3 + 2] = f2pk(tf[2], tf[2]);
    }
    __syncthreads();

    const ull M1  = f2pk(-1.f, -1.f);
    const ull TWO = f2pk(2.f, 2.f);

    PState st;
    st.PX = 0; st.PY = 0; st.PZ = 0; st.PW = f2pk(1.f, 1.f);
    st.TX = 0; st.TY = 0; st.TZ = 0;

    const int b0 = base + tid;
    const int b1 = b0 + TPB;
    float4* qu_out = (float4*)(out + (size_t)NL * BATCH * 3);

    // emit one link: compute, stage position in slot, store quats
    auto emit = [&](auto lc, int slot) {
        constexpr int L = decltype(lc)::value;
        float a0 = sQ[tid * NL + L];
        float a1 = sQ[(tid + TPB) * NL + L];
        float s0, c0, s1, c1;
        __sincosf(0.5f * a0, &s0, &c0);
        __sincosf(0.5f * a1, &s1, &c1);
        fk_step_pk<L>(st, sF[L*4+0], sF[L*4+1], sF[L*4+2], sF[L*4+3],
                      sV[L*3+0], sV[L*3+1], sV[L*3+2],
                      f2pk(s0, s1), f2pk(c0, c1), f2pk(-s0, -s1), M1, TWO);

        float x0, x1, y0, y1, z0, z1;
        f2upk(st.TX, x0, x1); f2upk(st.TY, y0, y1); f2upk(st.TZ, z0, z1);
        float* p0 = &sPos[slot * LPOSF + tid * 3];
        p0[0] = x0; p0[1] = y0; p0[2] = z0;
        float* p1 = &sPos[slot * LPOSF + (tid + TPB) * 3];
        p1[0] = x1; p1[1] = y1; p1[2] = z1;

        float qx0, qx1, qy0, qy1, qz0, qz1, qw0, qw1;
        f2upk(st.PX, qx0, qx1); f2upk(st.PY, qy0, qy1);
        f2upk(st.PZ, qz0, qz1); f2upk(st.PW, qw0, qw1);
        float g0 = (qw0 < 0.f) ? -1.f : 1.f;
        float g1 = (qw1 < 0.f) ? -1.f : 1.f;
        __stcs(&qu_out[(size_t)L * BATCH + b0],
               make_float4(g0 * qx0, g0 * qy0, g0 * qz0, g0 * qw0));
        __stcs(&qu_out[(size_t)L * BATCH + b1],
               make_float4(g1 * qx1, g1 * qy1, g1 * qz1, g1 * qw1));
    };

    // flush `n` staged link slots (links firstL..firstL+n-1), coalesced float4
    auto flush = [&](int firstL, int n) {
        const float4* sp4 = (const float4*)sPos;
        for (int j = tid; j < n * (LPOSF / 4); j += TPB) {
            int s   = j / (LPOSF / 4);
            int idx = j % (LPOSF / 4);
            float4* gp4 = (float4*)(out + ((size_t)(firstL + s) * BATCH + base) * 3);
            __stcs(&gp4[idx], sp4[j]);
        }
    };

    emit(std::integral_constant<int,0>{}, 0);
    emit(std::integral_constant<int,1>{}, 1);
    emit(std::integral_constant<int,2>{}, 2);
    emit(std::integral_constant<int,3>{}, 3);
    __syncthreads();
    flush(0, 4);
    __syncthreads();
    emit(std::integral_constant<int,4>{}, 0);
    emit(std::integral_constant<int,5>{}, 1);
    emit(std::integral_constant<int,6>{}, 2);
    __syncthreads();
    flush(4, 3);
}

extern "C" void kernel_launch(void* const* d_in, const int* in_sizes, int n_in,
                              void* d_out, int out_size) {
    const float* q           = (const float*)d_in[0];
    const float* rot_fixed   = (const float*)d_in[1];
    const float* trans_fixed = (const float*)d_in[2];
    float* out = (float*)d_out;

    fk_pk3_kernel<<<GRIDN, TPB>>>(q, rot_fixed, trans_fixed, out);
}